// round 1
// baseline (speedup 1.0000x reference)
#include <cuda_runtime.h>

#define D 64
#define MAXN 100000
#define TILE 128

// Scratch (static device arrays — no allocation allowed)
__device__ float g_agg[(size_t)MAXN * D];
__device__ float g_cnt[MAXN];
__device__ float g_h[(size_t)MAXN * D];

// ---------------------------------------------------------------------------
// Scatter: for each edge, agg[dst] += x[src] (vectorized L2 reduction),
// and (first pass only) cnt[dst] += 1.
// 16 threads per edge, one float4 each (row = 256B contiguous).
// ---------------------------------------------------------------------------
__global__ void scatter_kernel(const float4* __restrict__ xin,
                               const int* __restrict__ src,
                               const int* __restrict__ dst,
                               float* __restrict__ agg,
                               float* __restrict__ cnt,
                               int n_edges, int do_cnt) {
    int idx = blockIdx.x * blockDim.x + threadIdx.x;
    int e = idx >> 4;
    if (e >= n_edges) return;
    int lane = idx & 15;
    int s = __ldg(src + e);
    int d = __ldg(dst + e);
    float4 v = __ldg(xin + (size_t)s * 16 + lane);
    float* p = agg + (size_t)d * D + lane * 4;
    asm volatile("red.global.add.v4.f32 [%0], {%1,%2,%3,%4};"
                 :: "l"(p), "f"(v.x), "f"(v.y), "f"(v.z), "f"(v.w)
                 : "memory");
    if (do_cnt && lane == 0) atomicAdd(cnt + d, 1.0f);
}

// ---------------------------------------------------------------------------
// Combine: out[n] = (agg[n]/max(cnt,1)) @ Wl^T + b + x[n] @ Wr^T  (+ReLU)
// Block = 256 threads, TILE=128 nodes per block.
// Thread (fq = tid&15, g = tid>>4) computes 8 nodes x 4 features.
// Weights transposed in SMEM; node data staged k-major (transposed) so the
// inner-loop scalar reads are conflict-free.
// ---------------------------------------------------------------------------
__global__ void combine_kernel(const float* __restrict__ xin,
                               const float* __restrict__ agg,
                               const float* __restrict__ cnt,
                               const float* __restrict__ Wl,
                               const float* __restrict__ bl,
                               const float* __restrict__ Wr,
                               float* __restrict__ out,
                               int n_nodes, int do_relu) {
    extern __shared__ float sm[];
    float* wlT = sm;                 // [64][64]  wlT[k*64+f] = Wl[f][k]
    float* wrT = wlT + D * D;        // [64][64]
    float* xsT = wrT + D * D;        // [64][128] xsT[k*128+n]
    float* msT = xsT + D * TILE;     // [64][128]

    int tid = threadIdx.x;

    // stage transposed weights
    for (int i = tid; i < D * D; i += blockDim.x) {
        int f = i >> 6, k = i & 63;
        wlT[k * D + f] = Wl[i];
        wrT[k * D + f] = Wr[i];
    }

    int nb = blockIdx.x * TILE;

    // stage x and mean, transposed (k-major). 2048 float4 slots.
    for (int i = tid; i < TILE * 16; i += blockDim.x) {
        int n = i & (TILE - 1);      // 0..127 (consecutive threads -> consecutive n)
        int k4 = (i >> 7) * 4;       // 0,4,...,60
        int gn = nb + n;
        float4 xv = make_float4(0.f, 0.f, 0.f, 0.f);
        float4 av = make_float4(0.f, 0.f, 0.f, 0.f);
        float inv = 0.f;
        if (gn < n_nodes) {
            xv = __ldg((const float4*)(xin + (size_t)gn * D + k4));
            av = __ldg((const float4*)(agg + (size_t)gn * D + k4));
            inv = 1.0f / fmaxf(__ldg(cnt + gn), 1.0f);
        }
        xsT[(k4 + 0) * TILE + n] = xv.x;
        xsT[(k4 + 1) * TILE + n] = xv.y;
        xsT[(k4 + 2) * TILE + n] = xv.z;
        xsT[(k4 + 3) * TILE + n] = xv.w;
        msT[(k4 + 0) * TILE + n] = av.x * inv;
        msT[(k4 + 1) * TILE + n] = av.y * inv;
        msT[(k4 + 2) * TILE + n] = av.z * inv;
        msT[(k4 + 3) * TILE + n] = av.w * inv;
    }
    __syncthreads();

    int fq = tid & 15;   // feature quad: features 4*fq .. 4*fq+3
    int g  = tid >> 4;   // node group: nodes g, g+16, ..., g+112

    float4 b4 = __ldg((const float4*)(bl + fq * 4));
    float4 acc[8];
#pragma unroll
    for (int j = 0; j < 8; j++) acc[j] = b4;

    const float4* wl4 = (const float4*)wlT;
    const float4* wr4 = (const float4*)wrT;

#pragma unroll 4
    for (int k = 0; k < D; k++) {
        float4 wl = wl4[k * 16 + fq];
        float4 wr = wr4[k * 16 + fq];
#pragma unroll
        for (int j = 0; j < 8; j++) {
            int n = g + j * 16;
            float m  = msT[k * TILE + n];
            float xv = xsT[k * TILE + n];
            acc[j].x += m * wl.x + xv * wr.x;
            acc[j].y += m * wl.y + xv * wr.y;
            acc[j].z += m * wl.z + xv * wr.z;
            acc[j].w += m * wl.w + xv * wr.w;
        }
    }

#pragma unroll
    for (int j = 0; j < 8; j++) {
        int gn = nb + g + j * 16;
        if (gn < n_nodes) {
            float4 r = acc[j];
            if (do_relu) {
                r.x = fmaxf(r.x, 0.f);
                r.y = fmaxf(r.y, 0.f);
                r.z = fmaxf(r.z, 0.f);
                r.w = fmaxf(r.w, 0.f);
            }
            *(float4*)(out + (size_t)gn * D + fq * 4) = r;
        }
    }
}

// ---------------------------------------------------------------------------
extern "C" void kernel_launch(void* const* d_in, const int* in_sizes, int n_in,
                              void* d_out, int out_size) {
    const float* x   = (const float*)d_in[0];
    const int*   ei  = (const int*)  d_in[1];
    const float* W1l = (const float*)d_in[2];
    const float* b1l = (const float*)d_in[3];
    const float* W1r = (const float*)d_in[4];
    const float* W2l = (const float*)d_in[5];
    const float* b2l = (const float*)d_in[6];
    const float* W2r = (const float*)d_in[7];
    float* out = (float*)d_out;

    int n_nodes = in_sizes[0] / D;
    int n_edges = in_sizes[1] / 2;
    const int* src = ei;
    const int* dst = ei + n_edges;

    float *agg, *cnt, *h;
    cudaGetSymbolAddress((void**)&agg, g_agg);
    cudaGetSymbolAddress((void**)&cnt, g_cnt);
    cudaGetSymbolAddress((void**)&h,   g_h);

    const int SMEM = (2 * D * D + 2 * D * TILE) * (int)sizeof(float); // 96 KB
    cudaFuncSetAttribute(combine_kernel,
                         cudaFuncAttributeMaxDynamicSharedMemorySize, SMEM);

    int sblocks = (n_edges * 16 + 255) / 256;
    int cblocks = (n_nodes + TILE - 1) / TILE;

    // ---- Layer 1 ----
    cudaMemsetAsync(agg, 0, (size_t)n_nodes * D * sizeof(float));
    cudaMemsetAsync(cnt, 0, (size_t)n_nodes * sizeof(float));
    scatter_kernel<<<sblocks, 256>>>((const float4*)x, src, dst, agg, cnt,
                                     n_edges, 1);
    combine_kernel<<<cblocks, 256, SMEM>>>(x, agg, cnt, W1l, b1l, W1r, h,
                                           n_nodes, 1);

    // ---- Layer 2 (cnt reused) ----
    cudaMemsetAsync(agg, 0, (size_t)n_nodes * D * sizeof(float));
    scatter_kernel<<<sblocks, 256>>>((const float4*)h, src, dst, agg, cnt,
                                     n_edges, 0);
    combine_kernel<<<cblocks, 256, SMEM>>>(h, agg, cnt, W2l, b2l, W2r, out,
                                           n_nodes, 0);
}

// round 2
// speedup vs baseline: 1.3387x; 1.3387x over previous
#include <cuda_runtime.h>

#define D 64
#define MAXN 100000
#define MAXE 1600000
#define TILE 128

typedef unsigned long long u64;

// ---------------- static scratch (no allocation allowed) -------------------
__device__ float g_mean[(size_t)MAXN * D];
__device__ float g_h[(size_t)MAXN * D];
__device__ int   g_deg[MAXN];
__device__ int   g_rowptr[MAXN];
__device__ int   g_cursor[MAXN];
__device__ int   g_csrsrc[MAXE];
__device__ int   g_blocksums[128];
__device__ int   g_blockoffs[128];

// ---------------- f32x2 helpers (Blackwell packed fp32) --------------------
__device__ __forceinline__ u64 fma2(u64 a, u64 b, u64 c) {
    u64 d;
    asm("fma.rn.f32x2 %0, %1, %2, %3;" : "=l"(d) : "l"(a), "l"(b), "l"(c));
    return d;
}
__device__ __forceinline__ u64 pack2(float v) {
    u64 d;
    asm("mov.b64 %0, {%1, %1};" : "=l"(d) : "f"(v));
    return d;
}
__device__ __forceinline__ void unpack2(u64 v, float& lo, float& hi) {
    asm("mov.b64 {%0, %1}, %2;" : "=f"(lo), "=f"(hi) : "l"(v));
}

// ---------------- CSR build ------------------------------------------------
__global__ void count_kernel(const int* __restrict__ dst, int* __restrict__ deg,
                             int n_edges) {
    int e = blockIdx.x * blockDim.x + threadIdx.x;
    if (e < n_edges) atomicAdd(deg + __ldg(dst + e), 1);
}

// Exclusive scan of 1024-element chunks (Hillis-Steele). sums[b] = chunk total.
__global__ void scan_kernel(const int* __restrict__ in, int* __restrict__ out,
                            int* sums, int n) {
    __shared__ int sm[1024];
    int t = threadIdx.x;
    int i = blockIdx.x * 1024 + t;
    int v = (i < n) ? in[i] : 0;
    sm[t] = v;
    __syncthreads();
#pragma unroll
    for (int off = 1; off < 1024; off <<= 1) {
        int add = (t >= off) ? sm[t - off] : 0;
        __syncthreads();
        sm[t] += add;
        __syncthreads();
    }
    if (i < n) out[i] = sm[t] - v;            // exclusive
    if (sums != nullptr && t == 1023) sums[blockIdx.x] = sm[1023];
}

__global__ void add_off_kernel(int* __restrict__ rowptr, int* __restrict__ cursor,
                               const int* __restrict__ boffs, int n) {
    int i = blockIdx.x * blockDim.x + threadIdx.x;
    if (i < n) {
        int v = rowptr[i] + boffs[i >> 10];
        rowptr[i] = v;
        cursor[i] = v;
    }
}

__global__ void fill_kernel(const int* __restrict__ src, const int* __restrict__ dst,
                            int* __restrict__ cursor, int* __restrict__ csr,
                            int n_edges) {
    int e = blockIdx.x * blockDim.x + threadIdx.x;
    if (e < n_edges) {
        int d = __ldg(dst + e);
        int pos = atomicAdd(cursor + d, 1);
        csr[pos] = __ldg(src + e);
    }
}

// ---------------- aggregate: mean of in-neighbors (warp per node) ----------
__global__ void aggregate_kernel(const float2* __restrict__ x2,
                                 const int* __restrict__ csr,
                                 const int* __restrict__ rowptr,
                                 const int* __restrict__ deg,
                                 float2* __restrict__ mean2, int n_nodes) {
    int warp = (blockIdx.x * blockDim.x + threadIdx.x) >> 5;
    if (warp >= n_nodes) return;
    int lane = threadIdx.x & 31;
    int base = __ldg(rowptr + warp);
    int dg = __ldg(deg + warp);

    float2 a0 = {0.f, 0.f}, a1 = {0.f, 0.f}, a2 = {0.f, 0.f}, a3 = {0.f, 0.f};
    int j = 0;
    for (; j + 4 <= dg; j += 4) {
        int s0 = __ldg(csr + base + j);
        int s1 = __ldg(csr + base + j + 1);
        int s2 = __ldg(csr + base + j + 2);
        int s3 = __ldg(csr + base + j + 3);
        float2 v0 = __ldg(x2 + (size_t)s0 * 32 + lane);
        float2 v1 = __ldg(x2 + (size_t)s1 * 32 + lane);
        float2 v2 = __ldg(x2 + (size_t)s2 * 32 + lane);
        float2 v3 = __ldg(x2 + (size_t)s3 * 32 + lane);
        a0.x += v0.x; a0.y += v0.y;
        a1.x += v1.x; a1.y += v1.y;
        a2.x += v2.x; a2.y += v2.y;
        a3.x += v3.x; a3.y += v3.y;
    }
    for (; j < dg; j++) {
        int s = __ldg(csr + base + j);
        float2 v = __ldg(x2 + (size_t)s * 32 + lane);
        a0.x += v.x; a0.y += v.y;
    }
    float2 a;
    a.x = (a0.x + a1.x) + (a2.x + a3.x);
    a.y = (a0.y + a1.y) + (a2.y + a3.y);
    float inv = 1.0f / fmaxf((float)dg, 1.0f);
    a.x *= inv; a.y *= inv;
    mean2[(size_t)warp * 32 + lane] = a;
}

// ---------------- combine: out = mean@Wl^T + b + x@Wr^T (+ReLU) ------------
// 256 threads, 128 nodes/block. fq=tid&15 (4 features), g=tid>>4 (8 nodes as
// 2 contiguous quads). f32x2 packed along the node axis.
__global__ void combine_kernel(const float* __restrict__ xin,
                               const float* __restrict__ mean,
                               const float* __restrict__ Wl,
                               const float* __restrict__ bl,
                               const float* __restrict__ Wr,
                               float* __restrict__ out,
                               int n_nodes, int do_relu) {
    extern __shared__ float sm[];
    float* wlT = sm;                 // [64][64] wlT[k*64+f]
    float* wrT = wlT + D * D;
    float* xsT = wrT + D * D;        // [64][128] k-major
    float* msT = xsT + D * TILE;

    int tid = threadIdx.x;
    for (int i = tid; i < D * D; i += 256) {
        int f = i >> 6, k = i & 63;
        wlT[k * D + f] = Wl[i];
        wrT[k * D + f] = Wr[i];
    }
    int nb = blockIdx.x * TILE;
    for (int i = tid; i < TILE * 16; i += 256) {
        int n = i & (TILE - 1);
        int k4 = (i >> 7) * 4;
        int gn = nb + n;
        float4 xv = make_float4(0.f, 0.f, 0.f, 0.f);
        float4 mv = make_float4(0.f, 0.f, 0.f, 0.f);
        if (gn < n_nodes) {
            xv = __ldg((const float4*)(xin + (size_t)gn * D + k4));
            mv = __ldg((const float4*)(mean + (size_t)gn * D + k4));
        }
        xsT[(k4 + 0) * TILE + n] = xv.x;
        xsT[(k4 + 1) * TILE + n] = xv.y;
        xsT[(k4 + 2) * TILE + n] = xv.z;
        xsT[(k4 + 3) * TILE + n] = xv.w;
        msT[(k4 + 0) * TILE + n] = mv.x;
        msT[(k4 + 1) * TILE + n] = mv.y;
        msT[(k4 + 2) * TILE + n] = mv.z;
        msT[(k4 + 3) * TILE + n] = mv.w;
    }
    __syncthreads();

    int fq = tid & 15;
    int g = tid >> 4;

    float4 b4 = __ldg((const float4*)(bl + fq * 4));
    u64 acc[4][4];
    {
        u64 bp0 = pack2(b4.x), bp1 = pack2(b4.y), bp2 = pack2(b4.z), bp3 = pack2(b4.w);
#pragma unroll
        for (int p = 0; p < 4; p++) {
            acc[p][0] = bp0; acc[p][1] = bp1; acc[p][2] = bp2; acc[p][3] = bp3;
        }
    }

    const float4* wl4 = (const float4*)wlT;
    const float4* wr4 = (const float4*)wrT;
    const ulonglong2* msv = (const ulonglong2*)msT;   // 32 x u64x2 per k-row
    const ulonglong2* xsv = (const ulonglong2*)xsT;

#pragma unroll 4
    for (int k = 0; k < D; k++) {
        float4 wl = wl4[k * 16 + fq];
        float4 wr = wr4[k * 16 + fq];
        u64 wl2[4] = {pack2(wl.x), pack2(wl.y), pack2(wl.z), pack2(wl.w)};
        u64 wr2[4] = {pack2(wr.x), pack2(wr.y), pack2(wr.z), pack2(wr.w)};
        ulonglong2 m01 = msv[k * 32 + g];        // nodes 4g..4g+3
        ulonglong2 m23 = msv[k * 32 + 16 + g];   // nodes 64+4g..64+4g+3
        ulonglong2 x01 = xsv[k * 32 + g];
        ulonglong2 x23 = xsv[k * 32 + 16 + g];
#pragma unroll
        for (int f = 0; f < 4; f++) {
            acc[0][f] = fma2(m01.x, wl2[f], acc[0][f]);
            acc[0][f] = fma2(x01.x, wr2[f], acc[0][f]);
            acc[1][f] = fma2(m01.y, wl2[f], acc[1][f]);
            acc[1][f] = fma2(x01.y, wr2[f], acc[1][f]);
            acc[2][f] = fma2(m23.x, wl2[f], acc[2][f]);
            acc[2][f] = fma2(x23.x, wr2[f], acc[2][f]);
            acc[3][f] = fma2(m23.y, wl2[f], acc[3][f]);
            acc[3][f] = fma2(x23.y, wr2[f], acc[3][f]);
        }
    }

    // epilogue: pair p holds two nodes (lo, hi)
#pragma unroll
    for (int p = 0; p < 4; p++) {
        int nlo = (p < 2) ? (4 * g + 2 * p) : (64 + 4 * g + 2 * (p - 2));
        float lo[4], hi[4];
#pragma unroll
        for (int f = 0; f < 4; f++) unpack2(acc[p][f], lo[f], hi[f]);
        if (do_relu) {
#pragma unroll
            for (int f = 0; f < 4; f++) {
                lo[f] = fmaxf(lo[f], 0.f);
                hi[f] = fmaxf(hi[f], 0.f);
            }
        }
        int gn0 = nb + nlo;
        int gn1 = gn0 + 1;
        if (gn0 < n_nodes)
            *(float4*)(out + (size_t)gn0 * D + fq * 4) =
                make_float4(lo[0], lo[1], lo[2], lo[3]);
        if (gn1 < n_nodes)
            *(float4*)(out + (size_t)gn1 * D + fq * 4) =
                make_float4(hi[0], hi[1], hi[2], hi[3]);
    }
}

// ---------------------------------------------------------------------------
extern "C" void kernel_launch(void* const* d_in, const int* in_sizes, int n_in,
                              void* d_out, int out_size) {
    const float* x   = (const float*)d_in[0];
    const int*   ei  = (const int*)  d_in[1];
    const float* W1l = (const float*)d_in[2];
    const float* b1l = (const float*)d_in[3];
    const float* W1r = (const float*)d_in[4];
    const float* W2l = (const float*)d_in[5];
    const float* b2l = (const float*)d_in[6];
    const float* W2r = (const float*)d_in[7];
    float* out = (float*)d_out;

    int n_nodes = in_sizes[0] / D;
    int n_edges = in_sizes[1] / 2;
    const int* src = ei;
    const int* dst = ei + n_edges;

    float *mean, *h;
    int *deg, *rowptr, *cursor, *csr, *bsums, *boffs;
    cudaGetSymbolAddress((void**)&mean,   g_mean);
    cudaGetSymbolAddress((void**)&h,      g_h);
    cudaGetSymbolAddress((void**)&deg,    g_deg);
    cudaGetSymbolAddress((void**)&rowptr, g_rowptr);
    cudaGetSymbolAddress((void**)&cursor, g_cursor);
    cudaGetSymbolAddress((void**)&csr,    g_csrsrc);
    cudaGetSymbolAddress((void**)&bsums,  g_blocksums);
    cudaGetSymbolAddress((void**)&boffs,  g_blockoffs);

    const int SMEM = (2 * D * D + 2 * D * TILE) * (int)sizeof(float); // 96 KB
    cudaFuncSetAttribute(combine_kernel,
                         cudaFuncAttributeMaxDynamicSharedMemorySize, SMEM);

    int eblocks = (n_edges + 255) / 256;
    int nscan = (n_nodes + 1023) / 1024;
    int nblocks = (n_nodes + 255) / 256;
    int ablocks = (n_nodes * 32 + 255) / 256;
    int cblocks = (n_nodes + TILE - 1) / TILE;

    // ---- CSR build (once per call) ----
    cudaMemsetAsync(deg, 0, (size_t)n_nodes * sizeof(int));
    count_kernel<<<eblocks, 256>>>(dst, deg, n_edges);
    scan_kernel<<<nscan, 1024>>>(deg, rowptr, bsums, n_nodes);
    scan_kernel<<<1, 1024>>>(bsums, boffs, nullptr, nscan);
    add_off_kernel<<<nblocks, 256>>>(rowptr, cursor, boffs, n_nodes);
    fill_kernel<<<eblocks, 256>>>(src, dst, cursor, csr, n_edges);

    // ---- Layer 1 ----
    aggregate_kernel<<<ablocks, 256>>>((const float2*)x, csr, rowptr, deg,
                                       (float2*)mean, n_nodes);
    combine_kernel<<<cblocks, 256, SMEM>>>(x, mean, W1l, b1l, W1r, h,
                                           n_nodes, 1);

    // ---- Layer 2 ----
    aggregate_kernel<<<ablocks, 256>>>((const float2*)h, csr, rowptr, deg,
                                       (float2*)mean, n_nodes);
    combine_kernel<<<cblocks, 256, SMEM>>>(h, mean, W2l, b2l, W2r, out,
                                           n_nodes, 0);
}